// round 1
// baseline (speedup 1.0000x reference)
#include <cuda_runtime.h>
#include <math.h>

// ---------------------------------------------------------------- constants
#define DMODEL 1024
#define NHEADS 16
#define DK     64
#define DFF    4096
#define BATCH  2
#define SEQ    2048
#define MTOK   (BATCH*SEQ)   // 4096 tokens

// ---------------------------------------------------------------- scratch
// Static device scratch (allocation-free rule). ~721 MB.
static const long long SZ_TOK = (long long)MTOK * DMODEL;              // 4,194,304
static const long long SZ_S   = (long long)BATCH * NHEADS * SEQ * SEQ; // 134,217,728
static const long long SZ_H   = (long long)MTOK * DFF;                 // 16,777,216

static const long long OFF_Q   = 0;
static const long long OFF_K   = OFF_Q  + SZ_TOK;
static const long long OFF_V   = OFF_K  + SZ_TOK;
static const long long OFF_S   = OFF_V  + SZ_TOK;
static const long long OFF_CTX = OFF_S  + SZ_S;
static const long long OFF_AO  = OFF_CTX + SZ_TOK;
static const long long OFF_X1  = OFF_AO  + SZ_TOK;
static const long long OFF_H   = OFF_X1  + SZ_TOK;
static const long long OFF_FF  = OFF_H   + SZ_H;
static const long long TOTAL_F = OFF_FF  + SZ_TOK;   // 180,355,072 floats

__device__ float g_buf[180355072];

// ---------------------------------------------------------------- GEMM
// C[M,N] = alpha * A[M,K] * op(B) (+bias) (+gelu)
//   TRANSB=false: B is [K,N] row-major (ldb = row stride)
//   TRANSB=true : B is [N,K] row-major (ldb = row stride), computes A * B^T
// Batched via blockIdx.z with (outer=b, inner=h) stride decomposition.
// BM=128, BK=8 fixed; BN in {128,64}; TM=8; TN=BN/16; 256 threads.
// All dims must be exact multiples of tiles (true for every call here).
// EPI: 0 = alpha only, 1 = alpha + bias, 2 = alpha + bias + exact gelu.

__device__ __forceinline__ float gelu_exact(float v) {
    return 0.5f * v * (1.0f + erff(v * 0.70710678118654752f));
}

template<int BN, int TN, bool TRANSB, int EPI>
__global__ __launch_bounds__(256)
void gemm_k(const float* __restrict__ A, const float* __restrict__ B,
            const float* __restrict__ bias, float* __restrict__ C,
            int K, int lda, int ldb, int ldc, float alpha,
            long long aB, long long aH, long long bB, long long bH,
            long long cB, long long cH, int nH)
{
    constexpr int BM = 128, BK = 8, TM = 8;
    static_assert((BM/TM)*(BN/TN) == 256, "thread count");

    const int z  = blockIdx.z;
    const int zb = z / nH, zh = z % nH;
    A += (long long)zb * aB + (long long)zh * aH;
    B += (long long)zb * bB + (long long)zh * bH;
    C += (long long)zb * cB + (long long)zh * cH;

    __shared__ float As[BK][BM];
    __shared__ float Bs[BK][BN];

    const int tid    = threadIdx.x;
    const int rowBlk = blockIdx.y * BM;
    const int colBlk = blockIdx.x * BN;

    // compute-thread mapping: 16 x 16 grid of (TM x TN) micro-tiles
    const int tx   = tid & 15;
    const int ty   = tid >> 4;
    const int row0 = ty * TM;
    const int col0 = tx * TN;

    // A tile loader: 128x8 -> one float4 per thread
    const int arow = tid >> 1;
    const int acol = (tid & 1) * 4;

    float acc[TM][TN];
#pragma unroll
    for (int i = 0; i < TM; i++)
#pragma unroll
        for (int j = 0; j < TN; j++) acc[i][j] = 0.0f;

    for (int k0 = 0; k0 < K; k0 += BK) {
        // ---- load A tile (BM x BK), store transposed As[k][m]
        {
            float4 av = *(const float4*)(A + (long long)(rowBlk + arow) * lda + k0 + acol);
            As[acol + 0][arow] = av.x;
            As[acol + 1][arow] = av.y;
            As[acol + 2][arow] = av.z;
            As[acol + 3][arow] = av.w;
        }
        // ---- load B tile
        if constexpr (TRANSB) {
            // B is [N,K]: tile = BN rows x BK cols, float4 along k
            static_assert(BN == 128, "NT path assumes BN=128");
            const int n  = tid >> 1;
            const int kb = (tid & 1) * 4;
            float4 bv = *(const float4*)(B + (long long)(colBlk + n) * ldb + k0 + kb);
            Bs[kb + 0][n] = bv.x;
            Bs[kb + 1][n] = bv.y;
            Bs[kb + 2][n] = bv.z;
            Bs[kb + 3][n] = bv.w;
        } else if constexpr (BN == 128) {
            const int brow = tid >> 5;
            const int bcol = (tid & 31) * 4;
            float4 bv = *(const float4*)(B + (long long)(k0 + brow) * ldb + colBlk + bcol);
            *(float4*)&Bs[brow][bcol] = bv;
        } else { // BN == 64, NN
            const int brow = tid >> 5;
            const int bcol = (tid & 31) * 2;
            float2 bv = *(const float2*)(B + (long long)(k0 + brow) * ldb + colBlk + bcol);
            *(float2*)&Bs[brow][bcol] = bv;
        }
        __syncthreads();

#pragma unroll
        for (int kk = 0; kk < BK; kk++) {
            float ar[TM], br[TN];
            {
                float4 a0 = *(const float4*)&As[kk][row0];
                float4 a1 = *(const float4*)&As[kk][row0 + 4];
                ar[0]=a0.x; ar[1]=a0.y; ar[2]=a0.z; ar[3]=a0.w;
                ar[4]=a1.x; ar[5]=a1.y; ar[6]=a1.z; ar[7]=a1.w;
            }
#pragma unroll
            for (int j = 0; j < TN; j += 4) {
                float4 b0 = *(const float4*)&Bs[kk][col0 + j];
                br[j+0]=b0.x; br[j+1]=b0.y; br[j+2]=b0.z; br[j+3]=b0.w;
            }
#pragma unroll
            for (int i = 0; i < TM; i++)
#pragma unroll
                for (int j = 0; j < TN; j++)
                    acc[i][j] = fmaf(ar[i], br[j], acc[i][j]);
        }
        __syncthreads();
    }

    // ---- epilogue
    float bv[TN];
#pragma unroll
    for (int j = 0; j < TN; j++)
        bv[j] = (EPI >= 1) ? bias[colBlk + col0 + j] : 0.0f;

#pragma unroll
    for (int i = 0; i < TM; i++) {
        float* crow = C + (long long)(rowBlk + row0 + i) * ldc + colBlk + col0;
#pragma unroll
        for (int j = 0; j < TN; j += 4) {
            float4 o;
            float t0 = acc[i][j+0] * alpha;
            float t1 = acc[i][j+1] * alpha;
            float t2 = acc[i][j+2] * alpha;
            float t3 = acc[i][j+3] * alpha;
            if (EPI >= 1) { t0 += bv[j+0]; t1 += bv[j+1]; t2 += bv[j+2]; t3 += bv[j+3]; }
            if (EPI == 2) { t0 = gelu_exact(t0); t1 = gelu_exact(t1);
                            t2 = gelu_exact(t2); t3 = gelu_exact(t3); }
            o.x = t0; o.y = t1; o.z = t2; o.w = t3;
            *(float4*)(crow + j) = o;
        }
    }
}

// ---------------------------------------------------------------- softmax
// One block per score row. Applies mask (-1e9 where mask==0) then softmax.
__global__ __launch_bounds__(256)
void softmax_mask_k(float* __restrict__ sc, const int* __restrict__ mask)
{
    const int row = blockIdx.x;         // 0..SEQ-1 (query index)
    const int bh  = blockIdx.y;         // 0..B*H-1
    const int b   = bh / NHEADS;
    float* p = sc + ((long long)bh * SEQ + row) * SEQ;
    const int* mrow = mask + (long long)b * SEQ;

    const int t = threadIdx.x;
    constexpr int PER = SEQ / 256;      // 8
    float v[PER];
    float mx = -3.4e38f;
#pragma unroll
    for (int i = 0; i < PER; i++) {
        int c = t + i * 256;
        float x = p[c];
        if (mrow[c] == 0) x = -1e9f;
        v[i] = x;
        mx = fmaxf(mx, x);
    }
    __shared__ float red[256];
    red[t] = mx; __syncthreads();
    for (int s = 128; s > 0; s >>= 1) {
        if (t < s) red[t] = fmaxf(red[t], red[t + s]);
        __syncthreads();
    }
    mx = red[0];
    __syncthreads();

    float sum = 0.0f;
#pragma unroll
    for (int i = 0; i < PER; i++) {
        v[i] = __expf(v[i] - mx);
        sum += v[i];
    }
    red[t] = sum; __syncthreads();
    for (int s = 128; s > 0; s >>= 1) {
        if (t < s) red[t] += red[t + s];
        __syncthreads();
    }
    const float inv = 1.0f / red[0];
#pragma unroll
    for (int i = 0; i < PER; i++)
        p[t + i * 256] = v[i] * inv;
}

// ---------------------------------------------------------------- residual + LayerNorm
// out[row] = LN(a[row] + r[row]) * g + be,  D = 1024, one block/row
__global__ __launch_bounds__(256)
void add_ln_k(const float* __restrict__ a, const float* __restrict__ r,
              const float* __restrict__ g, const float* __restrict__ be,
              float* __restrict__ out)
{
    const long long row = blockIdx.x;
    const float* pa = a + row * DMODEL;
    const float* pr = r + row * DMODEL;
    float* po = out + row * DMODEL;
    const int t = threadIdx.x;
    constexpr int PER = DMODEL / 256;   // 4

    float v[PER];
    float s = 0.0f, s2 = 0.0f;
#pragma unroll
    for (int i = 0; i < PER; i++) {
        int c = t + i * 256;
        float x = pa[c] + pr[c];
        v[i] = x;
        s += x; s2 += x * x;
    }
    __shared__ float r1[256], r2[256];
    r1[t] = s; r2[t] = s2; __syncthreads();
    for (int st = 128; st > 0; st >>= 1) {
        if (t < st) { r1[t] += r1[t + st]; r2[t] += r2[t + st]; }
        __syncthreads();
    }
    const float mu  = r1[0] * (1.0f / DMODEL);
    const float var = r2[0] * (1.0f / DMODEL) - mu * mu;
    const float inv = rsqrtf(var + 1e-6f);
#pragma unroll
    for (int i = 0; i < PER; i++) {
        int c = t + i * 256;
        po[c] = (v[i] - mu) * inv * g[c] + be[c];
    }
}

// ---------------------------------------------------------------- launch
extern "C" void kernel_launch(void* const* d_in, const int* in_sizes, int n_in,
                              void* d_out, int out_size)
{
    const float* x    = (const float*)d_in[0];
    const int*   mask = (const int*)  d_in[1];
    const float* wq   = (const float*)d_in[2];
    const float* wk   = (const float*)d_in[3];
    const float* wv   = (const float*)d_in[4];
    const float* wo   = (const float*)d_in[5];
    const float* wo_b = (const float*)d_in[6];
    const float* w1   = (const float*)d_in[7];
    const float* b1   = (const float*)d_in[8];
    const float* w2   = (const float*)d_in[9];
    const float* b2   = (const float*)d_in[10];
    const float* g1   = (const float*)d_in[11];
    const float* be1  = (const float*)d_in[12];
    const float* g2   = (const float*)d_in[13];
    const float* be2  = (const float*)d_in[14];
    float* out = (float*)d_out;

    float* buf = nullptr;
    cudaGetSymbolAddress((void**)&buf, g_buf);
    float* Q   = buf + OFF_Q;
    float* Km  = buf + OFF_K;
    float* V   = buf + OFF_V;
    float* Sc  = buf + OFF_S;
    float* Ctx = buf + OFF_CTX;
    float* AO  = buf + OFF_AO;
    float* X1  = buf + OFF_X1;
    float* Hb  = buf + OFF_H;
    float* FF  = buf + OFF_FF;

    const dim3 blk(256);
    const long long tokStride = (long long)SEQ * DMODEL;
    const long long ssStride  = (long long)SEQ * SEQ;

    // ---- Q/K/V projections: [4096,1024] @ [1024,1024]
    {
        dim3 g(DMODEL / 128, MTOK / 128, 1);
        gemm_k<128, 8, false, 0><<<g, blk>>>(x, wq, nullptr, Q,
            DMODEL, DMODEL, DMODEL, DMODEL, 1.0f, 0, 0, 0, 0, 0, 0, 1);
        gemm_k<128, 8, false, 0><<<g, blk>>>(x, wk, nullptr, Km,
            DMODEL, DMODEL, DMODEL, DMODEL, 1.0f, 0, 0, 0, 0, 0, 0, 1);
        gemm_k<128, 8, false, 0><<<g, blk>>>(x, wv, nullptr, V,
            DMODEL, DMODEL, DMODEL, DMODEL, 1.0f, 0, 0, 0, 0, 0, 0, 1);
    }

    // ---- scores = scale * Q @ K^T, batched over (b,h)
    {
        dim3 g(SEQ / 128, SEQ / 128, BATCH * NHEADS);
        gemm_k<128, 8, true, 0><<<g, blk>>>(Q, Km, nullptr, Sc,
            DK, DMODEL, DMODEL, SEQ, 0.125f,
            tokStride, (long long)DK,               // A = Q  (b,h) offsets
            tokStride, (long long)DK,               // B = K
            (long long)NHEADS * ssStride, ssStride, // C = scores
            NHEADS);
    }

    // ---- mask + softmax (in place)
    softmax_mask_k<<<dim3(SEQ, BATCH * NHEADS), blk>>>(Sc, mask);

    // ---- ctx = P @ V, batched (N = 64 tile)
    {
        dim3 g(DK / 64, SEQ / 128, BATCH * NHEADS);
        gemm_k<64, 4, false, 0><<<g, blk>>>(Sc, V, nullptr, Ctx,
            SEQ, SEQ, DMODEL, DMODEL, 1.0f,
            (long long)NHEADS * ssStride, ssStride, // A = P
            tokStride, (long long)DK,               // B = V
            tokStride, (long long)DK,               // C = ctx (head-interleaved)
            NHEADS);
    }

    // ---- attn_out = ctx @ wo + wo_b
    gemm_k<128, 8, false, 1><<<dim3(DMODEL / 128, MTOK / 128, 1), blk>>>(
        Ctx, wo, wo_b, AO, DMODEL, DMODEL, DMODEL, DMODEL, 1.0f,
        0, 0, 0, 0, 0, 0, 1);

    // ---- x1 = LN(x + attn_out)
    add_ln_k<<<MTOK, blk>>>(x, AO, g1, be1, X1);

    // ---- h = gelu(x1 @ w1 + b1)
    gemm_k<128, 8, false, 2><<<dim3(DFF / 128, MTOK / 128, 1), blk>>>(
        X1, w1, b1, Hb, DMODEL, DMODEL, DFF, DFF, 1.0f,
        0, 0, 0, 0, 0, 0, 1);

    // ---- ff = h @ w2 + b2
    gemm_k<128, 8, false, 1><<<dim3(DMODEL / 128, MTOK / 128, 1), blk>>>(
        Hb, w2, b2, FF, DFF, DFF, DMODEL, DMODEL, 1.0f,
        0, 0, 0, 0, 0, 0, 1);

    // ---- out = LN(x1 + ff)
    add_ln_k<<<MTOK, blk>>>(X1, FF, g2, be2, out);
}